// round 9
// baseline (speedup 1.0000x reference)
#include <cuda_runtime.h>
#include <stdint.h>

// Problem constants
#define NB       64
#define NH       512
#define NUM_MASK 3072          // masked patches per image
#define NTILES   4096          // 64 images * 64 patch-rows
#define NBLOCKS  592           // 148 SMs * 4 blocks/SM -> single persistent wave

// ---------------------------------------------------------------------------
// Persistent fused kernel. 592 blocks of 384 threads, each grid-striding
// over 4096 (image, patch-row) tiles (~7 tiles/block). Blocks never exit,
// so the DRAM pipeline never drains at wave boundaries (the ~7us gap the
// 7-wave R4 launch showed as DRAM active at only 67%).
//
// Per tile (identical to the proven R4 body):
//  Prologue: build the tile's 64-patch masked bitmap from mask_indices
//  (each thread reads 8 of the image's 3072 indices, coalesced, L2-hit;
//  range-test + atomicOr into 2 shared words).
//  Main: each thread owns one float4 column across the 8 rows of the patch
//  band. keep: 8x LDG.128 front-batched (MLP=8) + 8x STG.128.
//        drop: 8x STG.128 of zeros, image never read (75% read savings).
//  Row stride = 384 float4 = 6144 B; fully coalesced.
__global__ void __launch_bounds__(384)
random_mask_kernel(const float4* __restrict__ img,
                   const int*    __restrict__ mask_indices,
                   float4*       __restrict__ out) {
    const int t = threadIdx.x;            // float4 col [0, 384)
    __shared__ uint32_t masked_bits[2];

    for (int tile = blockIdx.x; tile < NTILES; tile += NBLOCKS) {
        const int pr = tile & 63;         // patch row [0, 64)
        const int b  = tile >> 6;         // image     [0, 64)

        // ---- build 64-bit masked-bitmap for this (image, patch-row) ----
        if (t < 2) masked_bits[t] = 0;
        __syncthreads();

        const int* mi = mask_indices + b * NUM_MASK;
        const int lo = pr << 6;           // first patch id of this row
#pragma unroll
        for (int j = 0; j < 8; j++) {
            int idx = mi[t + j * 384];    // coalesced, L2-resident
            unsigned d = (unsigned)(idx - lo);
            if (d < 64u) atomicOr(&masked_bits[d >> 5], 1u << (d & 31));
        }
        __syncthreads();

        const int p = t / 6;              // patch col: 6 float4 per patch
        const bool keep = !((masked_bits[p >> 5] >> (p & 31)) & 1u);

        // ---- stream the 8-row band ----
        const long base = ((long)(b * NH + (pr << 3)) * 384) + t;
        const float4* ip = img + base;
        float4*       op = out + base;

        if (keep) {
            float4 v[8];
#pragma unroll
            for (int r = 0; r < 8; r++) v[r] = __ldcs(ip + r * 384);
#pragma unroll
            for (int r = 0; r < 8; r++) __stcs(op + r * 384, v[r]);
        } else {
            const float4 z = make_float4(0.f, 0.f, 0.f, 0.f);
#pragma unroll
            for (int r = 0; r < 8; r++) __stcs(op + r * 384, z);
        }

        // protect masked_bits before next iteration's re-init
        __syncthreads();
    }
}

// ---------------------------------------------------------------------------
extern "C" void kernel_launch(void* const* d_in, const int* in_sizes, int n_in,
                              void* d_out, int out_size) {
    const float4* img = (const float4*)d_in[0];       // images [64,512,512,3] f32
    const int* mask_indices = (const int*)d_in[1];    // [64, 3072] i32
    float4* out = (float4*)d_out;

    random_mask_kernel<<<NBLOCKS, 384>>>(img, mask_indices, out);
}

// round 10
// speedup vs baseline: 1.1332x; 1.1332x over previous
#include <cuda_runtime.h>
#include <stdint.h>

// Problem constants
#define NB       64
#define NH       512
#define NUM_MASK 3072          // masked patches per image

// ---------------------------------------------------------------------------
// Single fused kernel — R4 structure with 256-bit (v8.f32) global accesses
// (sm_10x LDG.256/STG.256). Grid (64 patch-rows, 64 images), 384 threads.
//
// A row = 512px*3ch*4B = 6144 B = 192 x 32B (f8). Thread t -> column
// col = t % 192, row-half sub = t / 192 (rows sub*4 .. sub*4+3 of the
// 8-row patch band). Lanes of a warp touch 32 consecutive f8 = 1024 B
// contiguous per access (vs 512 B with float4) — longer DRAM bursts.
// Patch col: 96 B per patch = 3 f8 -> p = col/3; both halves of the band
// share the same patch bit.
//
// Prologue (unchanged from R4): build the 64-patch masked bitmap from
// mask_indices (8 coalesced L2-hit loads/thread, atomicOr into 2 smem words).
//
// Main: keep -> 4x LDG.256 front-batched (128 B in flight/thread, same as
// R4) + 4x STG.256; drop -> 4x STG.256 of zeros, image never read
// (saves 75% of read traffic).
__global__ void __launch_bounds__(384)
random_mask_kernel(const float* __restrict__ img,
                   const int*   __restrict__ mask_indices,
                   float*       __restrict__ out) {
    const int pr = blockIdx.x;            // patch row   [0, 64)
    const int b  = blockIdx.y;            // image       [0, 64)
    const int t  = threadIdx.x;           // [0, 384)

    // ---- build 64-bit masked-bitmap for this (image, patch-row) ----
    __shared__ uint32_t masked_bits[2];
    if (t < 2) masked_bits[t] = 0;
    __syncthreads();

    const int* mi = mask_indices + b * NUM_MASK;
    const int lo = pr << 6;               // first patch id of this row
#pragma unroll
    for (int j = 0; j < 8; j++) {
        int idx = mi[t + j * 384];        // coalesced, L2-resident
        unsigned d = (unsigned)(idx - lo);
        if (d < 64u) atomicOr(&masked_bits[d >> 5], 1u << (d & 31));
    }
    __syncthreads();

    const int col = t % 192;              // f8 column within row [0, 192)
    const int sub = t / 192;              // 0: rows 0-3, 1: rows 4-7
    const int p   = col / 3;              // patch: 3 f8 (96 B) per patch
    const bool keep = !((masked_bits[p >> 5] >> (p & 31)) & 1u);

    // ---- stream 4 rows, one f8 (32 B) per row ----
    // float index of first element: (row * 192 + col) * 8
    const long base = ((long)(b * NH + (pr << 3) + (sub << 2)) * 192 + col) * 8;
    const float* ip = img + base;
    float*       op = out + base;
    const int rs = 192 * 8;               // row stride in floats

    float v[32];
#pragma unroll
    for (int i = 0; i < 32; i++) v[i] = 0.f;

    if (keep) {
#pragma unroll
        for (int r = 0; r < 4; r++) {
            const float* a = ip + r * rs;
            asm volatile(
                "ld.global.cs.v8.f32 {%0,%1,%2,%3,%4,%5,%6,%7}, [%8];"
                : "=f"(v[r*8+0]), "=f"(v[r*8+1]), "=f"(v[r*8+2]), "=f"(v[r*8+3]),
                  "=f"(v[r*8+4]), "=f"(v[r*8+5]), "=f"(v[r*8+6]), "=f"(v[r*8+7])
                : "l"(a));
        }
    }

#pragma unroll
    for (int r = 0; r < 4; r++) {
        float* a = op + r * rs;
        asm volatile(
            "st.global.cs.v8.f32 [%0], {%1,%2,%3,%4,%5,%6,%7,%8};"
            :: "l"(a),
               "f"(v[r*8+0]), "f"(v[r*8+1]), "f"(v[r*8+2]), "f"(v[r*8+3]),
               "f"(v[r*8+4]), "f"(v[r*8+5]), "f"(v[r*8+6]), "f"(v[r*8+7])
            : "memory");
    }
}

// ---------------------------------------------------------------------------
extern "C" void kernel_launch(void* const* d_in, const int* in_sizes, int n_in,
                              void* d_out, int out_size) {
    const float* img = (const float*)d_in[0];         // images [64,512,512,3] f32
    const int* mask_indices = (const int*)d_in[1];    // [64, 3072] i32
    float* out = (float*)d_out;

    dim3 grid(64, NB);                    // (patch-rows, images)
    random_mask_kernel<<<grid, 384>>>(img, mask_indices, out);
}

// round 11
// speedup vs baseline: 1.1347x; 1.0013x over previous
#include <cuda_runtime.h>
#include <stdint.h>

// Problem constants
#define NB       64
#define NH       512
#define NW       512
#define NC       3
#define NUM_MASK 3072          // masked patches per image

// ---------------------------------------------------------------------------
// Single fused kernel (converged optimum — R4 configuration).
// Grid (NPH=64 patch-rows, NB=64 images); block = 384 threads.
//
// Prologue: build this block's 64-patch keep bitmap directly from
// mask_indices (no intermediate global mask, no builder kernel):
//   - each thread reads 8 indices of this image's 3072 (coalesced; the
//     12 KB slice is shared by 64 blocks -> L2 resident)
//   - range-test against this patch-row, atomicOr into 2 shared words.
//
// Main: a patch spans 8 consecutive rows sharing one mask bit. Each thread
// owns one float4 column across the 8 rows of its patch band:
//   - keep: 8x LDG.128 (front-batched -> MLP=8) + 8x STG.128
//   - drop: 8x STG.128 of zeros, image never read (saves 75% read traffic)
// Consecutive threads touch consecutive float4s within a row -> fully
// coalesced. Row stride = 384 float4 = 6144 B.
//
// Tuning history (all single-axis probes off this base): more occupancy,
// larger tiles, deeper per-thread MLP, default-store policy, persistent
// blocks, and 256-bit v8 accesses ALL regressed or tied. This point is the
// ridge top: 252 MB at ~5.8 TB/s effective (~73% of HBM spec).
__global__ void __launch_bounds__(384)
random_mask_kernel(const float4* __restrict__ img,
                   const int*    __restrict__ mask_indices,
                   float4*       __restrict__ out) {
    const int pr = blockIdx.x;            // patch row   [0, 64)
    const int b  = blockIdx.y;            // image       [0, 64)
    const int t  = threadIdx.x;           // float4 col  [0, 384)

    // ---- build 64-bit masked-bitmap for this (image, patch-row) ----
    __shared__ uint32_t masked_bits[2];
    if (t < 2) masked_bits[t] = 0;
    __syncthreads();

    const int* mi = mask_indices + b * NUM_MASK;
    const int lo = pr << 6;               // first patch id of this row
#pragma unroll
    for (int j = 0; j < 8; j++) {
        int idx = mi[t + j * 384];        // coalesced, L2-resident
        unsigned d = (unsigned)(idx - lo);
        if (d < 64u) atomicOr(&masked_bits[d >> 5], 1u << (d & 31));
    }
    __syncthreads();

    const int p = t / 6;                  // patch col: 6 float4 per patch
    const bool keep = !((masked_bits[p >> 5] >> (p & 31)) & 1u);

    // ---- stream the 8-row band ----
    const long base = ((long)(b * NH + (pr << 3)) * 384) + t;
    const float4* ip = img + base;
    float4*       op = out + base;

    if (keep) {
        float4 v[8];
#pragma unroll
        for (int r = 0; r < 8; r++) v[r] = __ldcs(ip + r * 384);
#pragma unroll
        for (int r = 0; r < 8; r++) __stcs(op + r * 384, v[r]);
    } else {
        const float4 z = make_float4(0.f, 0.f, 0.f, 0.f);
#pragma unroll
        for (int r = 0; r < 8; r++) __stcs(op + r * 384, z);
    }
}

// ---------------------------------------------------------------------------
extern "C" void kernel_launch(void* const* d_in, const int* in_sizes, int n_in,
                              void* d_out, int out_size) {
    const float4* img = (const float4*)d_in[0];       // images [64,512,512,3] f32
    const int* mask_indices = (const int*)d_in[1];    // [64, 3072] i32
    float4* out = (float4*)d_out;

    dim3 grid(64, NB);                    // (patch-rows, images)
    random_mask_kernel<<<grid, 384>>>(img, mask_indices, out);
}